// round 15
// baseline (speedup 1.0000x reference)
#include <cuda_runtime.h>
#include <cstdint>

// ---------------------------------------------------------------------------
// GRUSeq2Seq on GB300 (sm_103a) — round 15
// Layer-skewed 2-phase steps; 6-group balanced split with C=4.
// 147 CTAs x 14 rows. NT=576 = 6 groups x 96 threads, cols jc,+96,+192,+288.
// Encoder units {17,17,17,17,16,16} (W0i folded into grp1/3); decoder 16 each.
// All gate buffers 2-partial. All nonlinearities via tanh.approx.f32 (MUFU).
// fp32 via fma.rn.f32x2, zero weight-load redundancy.
// ---------------------------------------------------------------------------

#define HID   128
#define NFEAT 16
#define TIN   336
#define TOUT  168
#define BATCH 2048
#define NP    7
#define NROW  14
#define NT    576
#define NBLK  147
#define GB    2688        // ull per gate buffer (NP*384)

typedef unsigned long long ull;

__device__ float g_We0i[NFEAT * 384];  // float4 layout [k/4][384][4]
__device__ float g_We0h[HID * 384];
__device__ float g_We1i[HID * 384];
__device__ float g_We1h[HID * 384];
__device__ float g_Wd0h[HID * 384];
__device__ float g_Wd1i[HID * 384];
__device__ float g_Wd1h[HID * 384];
__device__ float g_Wfc1[HID * 64];     // pair layout [k/2][64][2]

__device__ __forceinline__ ull pk2(float lo, float hi) {
    ull r;
    asm("mov.b64 %0, {%1, %2};" : "=l"(r) : "f"(lo), "f"(hi));
    return r;
}
__device__ __forceinline__ float2 upk(ull v) {
    float a, b;
    asm("mov.b64 {%0, %1}, %2;" : "=f"(a), "=f"(b) : "l"(v));
    return make_float2(a, b);
}
__device__ __forceinline__ ull ffma2(ull a, ull b, ull c) {
    ull d;
    asm("fma.rn.f32x2 %0, %1, %2, %3;" : "=l"(d) : "l"(a), "l"(b), "l"(c));
    return d;
}
__device__ __forceinline__ ull add2(ull a, ull b) {
    ull d;
    asm("add.rn.f32x2 %0, %1, %2;" : "=l"(d) : "l"(a), "l"(b));
    return d;
}
// sigmoid via HW tanh: sigma(v) = 0.5*tanh(v/2) + 0.5   (1 MUFU)
__device__ __forceinline__ float sigmf(float v) {
    float t;
    asm("tanh.approx.f32 %0, %1;" : "=f"(t) : "f"(0.5f * v));
    return fmaf(0.5f, t, 0.5f);
}
// n-gate tanh via HW tanh (validated: sigmoid path cost only ~1e-6 rel err)
__device__ __forceinline__ float tanh_f(float v) {
    float t;
    asm("tanh.approx.f32 %0, %1;" : "=f"(t) : "f"(v));
    return t;
}

// ------------------------- quad-column GEMM segment -------------------------
// Thread computes columns jc, jc+96, jc+192, jc+288 for all NP row-pairs over
// k4 range [k4b, k4b+N4). h reads are warp-uniform broadcasts.
template <int K, int N4>
__device__ __forceinline__ void gemm4(const float* __restrict__ Wf,
                                      const ull* __restrict__ hs,
                                      ull* __restrict__ dst,
                                      int jc, int k4b) {
    const float4* W4 = reinterpret_cast<const float4*>(Wf);
    ull a0[NP], a1[NP], a2[NP], a3[NP];
#pragma unroll
    for (int p = 0; p < NP; p++) {
        a0[p] = 0ull; a1[p] = 0ull; a2[p] = 0ull; a3[p] = 0ull;
    }
#pragma unroll 2
    for (int i = 0; i < N4; i++) {
        const int k4 = k4b + i;
        const float4* wrow = &W4[k4 * 384 + jc];
        float4 wA = __ldg(wrow);
        float4 wB = __ldg(wrow + 96);
        float4 wC = __ldg(wrow + 192);
        float4 wD = __ldg(wrow + 288);
        ull wa0 = pk2(wA.x, wA.x), wa1 = pk2(wA.y, wA.y);
        ull wa2 = pk2(wA.z, wA.z), wa3 = pk2(wA.w, wA.w);
        ull wb0 = pk2(wB.x, wB.x), wb1 = pk2(wB.y, wB.y);
        ull wb2 = pk2(wB.z, wB.z), wb3 = pk2(wB.w, wB.w);
        ull wc0 = pk2(wC.x, wC.x), wc1 = pk2(wC.y, wC.y);
        ull wc2 = pk2(wC.z, wC.z), wc3 = pk2(wC.w, wC.w);
        ull wd0 = pk2(wD.x, wD.x), wd1 = pk2(wD.y, wD.y);
        ull wd2 = pk2(wD.z, wD.z), wd3 = pk2(wD.w, wD.w);
#pragma unroll
        for (int p = 0; p < NP; p++) {
            const ull* hp = &hs[p * K + 4 * k4];
            ulonglong2 h01 = *reinterpret_cast<const ulonglong2*>(hp);
            ulonglong2 h23 = *reinterpret_cast<const ulonglong2*>(hp + 2);
            a0[p] = ffma2(h01.x, wa0, a0[p]);
            a1[p] = ffma2(h01.x, wb0, a1[p]);
            a2[p] = ffma2(h01.x, wc0, a2[p]);
            a3[p] = ffma2(h01.x, wd0, a3[p]);
            a0[p] = ffma2(h01.y, wa1, a0[p]);
            a1[p] = ffma2(h01.y, wb1, a1[p]);
            a2[p] = ffma2(h01.y, wc1, a2[p]);
            a3[p] = ffma2(h01.y, wd1, a3[p]);
            a0[p] = ffma2(h23.x, wa2, a0[p]);
            a1[p] = ffma2(h23.x, wb2, a1[p]);
            a2[p] = ffma2(h23.x, wc2, a2[p]);
            a3[p] = ffma2(h23.x, wd2, a3[p]);
            a0[p] = ffma2(h23.y, wa3, a0[p]);
            a1[p] = ffma2(h23.y, wb3, a1[p]);
            a2[p] = ffma2(h23.y, wc3, a2[p]);
            a3[p] = ffma2(h23.y, wd3, a3[p]);
        }
    }
#pragma unroll
    for (int p = 0; p < NP; p++) {
        dst[p * 384 + jc]       = a0[p];
        dst[p * 384 + jc + 96]  = a1[p];
        dst[p * 384 + jc + 192] = a2[p];
        dst[p * 384 + jc + 288] = a3[p];
    }
}

// ------------------------- GRU core ----------------------------------------
__device__ __forceinline__ ull gru_core(float2 ir, float2 iz, float2 inn,
                                        float2 hr, float2 hz, float2 hn,
                                        float4 bb, ull hold) {
    float2 h = upk(hold);
    float rx = sigmf(ir.x + hr.x + bb.x);
    float ry = sigmf(ir.y + hr.y + bb.x);
    float zx = sigmf(iz.x + hz.x + bb.y);
    float zy = sigmf(iz.y + hz.y + bb.y);
    float nx = tanh_f(inn.x + bb.z + rx * (hn.x + bb.w));
    float ny = tanh_f(inn.y + bb.z + ry * (hn.y + bb.w));
    return pk2((1.0f - zx) * nx + zx * h.x, (1.0f - zy) * ny + zy * h.y);
}

// gates: gi dual partials, gh dual partials
__device__ __forceinline__ void gate_dd(ull* hs, const ull* gi, const ull* gh,
                                        const float4* b4, int i) {
    int u = i & (HID - 1);
    int p = i >> 7;
    int b0 = p * 384 + u;
    float2 ir  = upk(add2(gi[b0], gi[b0 + GB]));
    float2 iz  = upk(add2(gi[b0 + HID], gi[b0 + HID + GB]));
    float2 inn = upk(add2(gi[b0 + 2 * HID], gi[b0 + 2 * HID + GB]));
    float2 hr  = upk(add2(gh[b0], gh[b0 + GB]));
    float2 hz  = upk(add2(gh[b0 + HID], gh[b0 + HID + GB]));
    float2 hn  = upk(add2(gh[b0 + 2 * HID], gh[b0 + 2 * HID + GB]));
    hs[p * HID + u] = gru_core(ir, iz, inn, hr, hz, hn, b4[u],
                               hs[p * HID + u]);
}

// decoder cell-0 gates: gh dual partials, gi = pred * dwih0 folded in
__device__ __forceinline__ void gate_d0(ull* hs, const ull* gh,
                                        const ull* pred2, const float4* dw4,
                                        const float4* b4, int i) {
    int u = i & (HID - 1);
    int p = i >> 7;
    int b0 = p * 384 + u;
    float2 pr = upk(pred2[p]);
    float4 w = dw4[u];
    float2 ir = make_float2(pr.x * w.x, pr.y * w.x);
    float2 iz = make_float2(pr.x * w.y, pr.y * w.y);
    float2 inn = make_float2(pr.x * w.z, pr.y * w.z);
    float2 hr = upk(add2(gh[b0], gh[b0 + GB]));
    float2 hz = upk(add2(gh[b0 + HID], gh[b0 + HID + GB]));
    float2 hn = upk(add2(gh[b0 + 2 * HID], gh[b0 + 2 * HID + GB]));
    hs[p * HID + u] = gru_core(ir, iz, inn, hr, hz, hn, b4[u],
                               hs[p * HID + u]);
}

// ------------------------- fused weight transform ---------------------------
__global__ void tr_all(const float* __restrict__ w0, const float* __restrict__ w1,
                       const float* __restrict__ w2, const float* __restrict__ w3,
                       const float* __restrict__ w4, const float* __restrict__ w5,
                       const float* __restrict__ w6, const float* __restrict__ w7) {
    int i = blockIdx.x * blockDim.x + threadIdx.x;
    const int n0 = NFEAT * 384;
    const int nH = HID * 384;
    const int n7 = HID * 64;
    int seg, off;
    if (i < n0) { seg = 0; off = i; }
    else if (i < n0 + 6 * nH) { seg = 1 + (i - n0) / nH; off = (i - n0) % nH; }
    else if (i < n0 + 6 * nH + n7) { seg = 7; off = i - n0 - 6 * nH; }
    else return;

    const float* src = seg == 0 ? w0 : seg == 1 ? w1 : seg == 2 ? w2
                     : seg == 3 ? w3 : seg == 4 ? w4 : seg == 5 ? w5
                     : seg == 6 ? w6 : w7;
    float* dst = seg == 0 ? g_We0i : seg == 1 ? g_We0h : seg == 2 ? g_We1i
               : seg == 3 ? g_We1h : seg == 4 ? g_Wd0h : seg == 5 ? g_Wd1i
               : seg == 6 ? g_Wd1h : g_Wfc1;
    int K = seg == 0 ? NFEAT : HID;
    int J = seg == 7 ? 64 : 384;
    int j = off / K;
    int k = off % K;
    float v = src[off];
    if (seg == 7)
        dst[(k >> 1) * (2 * J) + 2 * j + (k & 1)] = v;
    else
        dst[(k >> 2) * (4 * J) + 4 * j + (k & 3)] = v;
}

// ------------------------- shared memory layout (ull units) -----------------
// h0s 896 | h1s 896 | xs 224 | gi0 2GB | gh0 2GB | gi1 2GB | gh1 2GB | pred2 8
// b4 tables 4*128 float4 (1024 ull) | dw4 128 float4 (256) | sfcb1+sw2 (64)
#define SM_ULL (896 + 896 + 224 + 8*GB + 8 + 1024 + 256 + 64)
#define SMEM_BYTES (SM_ULL * 8)   // 198,976 B

__global__ void __launch_bounds__(NT) gru_main(
    const float* __restrict__ x,
    const float* __restrict__ be_ih0, const float* __restrict__ be_hh0,
    const float* __restrict__ be_ih1, const float* __restrict__ be_hh1,
    const float* __restrict__ dwih0,
    const float* __restrict__ bd_ih0, const float* __restrict__ bd_hh0,
    const float* __restrict__ bd_ih1, const float* __restrict__ bd_hh1,
    const float* __restrict__ fcb1, const float* __restrict__ fcw2,
    const float* __restrict__ fcb2,
    float* __restrict__ out) {
    extern __shared__ ull sm[];
    ull* h0s = sm;                 // 896
    ull* h1s = h0s + 896;          // 896
    ull* xs  = h1s + 896;          // 224 (double-buffered 112)
    ull* gi0 = xs + 224;           // 2GB
    ull* gh0 = gi0 + 2 * GB;       // 2GB
    ull* gi1 = gh0 + 2 * GB;       // 2GB
    ull* gh1 = gi1 + 2 * GB;       // 2GB
    ull* pred2 = gh1 + 2 * GB;     // 8
    float4* b4e0 = reinterpret_cast<float4*>(pred2 + 8);   // 128 each
    float4* b4e1 = b4e0 + 128;
    float4* b4d0 = b4e1 + 128;
    float4* b4d1 = b4d0 + 128;
    float4* dw4  = b4d1 + 128;     // 128
    float* sfcb1 = reinterpret_cast<float*>(dw4 + 128);    // 64
    float* sw2   = sfcb1 + 64;

    const int tid = threadIdx.x;
    const int grp = tid / 96;      // 0..5, warp-uniform (96 = 3 warps)
    const int jc  = tid % 96;      // columns jc, +96, +192, +288
    const int rowbase = blockIdx.x * NROW;

    // ---- init ----
    for (int i = tid; i < 1792; i += NT) h0s[i] = 0ull;
    if (tid < 512) {
        int type = tid >> 7, u = tid & 127;
        const float* bi = type == 0 ? be_ih0 : type == 1 ? be_ih1
                        : type == 2 ? bd_ih0 : bd_ih1;
        const float* bh = type == 0 ? be_hh0 : type == 1 ? be_hh1
                        : type == 2 ? bd_hh0 : bd_hh1;
        float4* dst4 = type == 0 ? b4e0 : type == 1 ? b4e1
                     : type == 2 ? b4d0 : b4d1;
        dst4[u] = make_float4(bi[u] + bh[u], bi[HID + u] + bh[HID + u],
                              bi[2 * HID + u], bh[2 * HID + u]);
    }
    if (tid < 128)
        dw4[tid] = make_float4(dwih0[tid], dwih0[HID + tid],
                               dwih0[2 * HID + tid], 0.0f);
    if (tid < 64) {
        sfcb1[tid] = fcb1[tid];
        sw2[tid] = fcw2[tid];
    }
    if (tid < 8) pred2[tid] = 0ull;
    for (int i = tid; i < NP * NFEAT; i += NT) {
        int p = i >> 4, c = i & 15;
        int ra = rowbase + 2 * p, rb = ra + 1;
        if (ra > BATCH - 1) ra = BATCH - 1;
        if (rb > BATCH - 1) rb = BATCH - 1;
        xs[p * NFEAT + c] = pk2(x[(size_t)ra * TIN * NFEAT + c],
                                x[(size_t)rb * TIN * NFEAT + c]);
    }
    __syncthreads();

    // ====================== encoder (layer1 skewed by 1) ====================
    for (int t = 0; t <= TIN; t++) {
        // Phase A: stage x(t+1); balanced gemm segments l0(t) + l1(t-1)
        if (t + 1 < TIN) {
            ull* xd = xs + ((t + 1) & 1) * 112;
            for (int i = tid; i < NP * NFEAT; i += NT) {
                int p = i >> 4, c = i & 15;
                int ra = rowbase + 2 * p, rb = ra + 1;
                if (ra > BATCH - 1) ra = BATCH - 1;
                if (rb > BATCH - 1) rb = BATCH - 1;
                xd[p * NFEAT + c] =
                    pk2(x[(size_t)ra * TIN * NFEAT + (size_t)(t + 1) * NFEAT + c],
                        x[(size_t)rb * TIN * NFEAT + (size_t)(t + 1) * NFEAT + c]);
            }
        }
        const ull* xcur = xs + (t & 1) * 112;
        if (grp == 0) {
            if (t < TIN) gemm4<HID, 17>(g_We0h, h0s, gh0, jc, 0);
        } else if (grp == 1) {
            if (t < TIN) {
                gemm4<HID, 15>(g_We0h, h0s, gh0 + GB, jc, 17);
                gemm4<NFEAT, 2>(g_We0i, xcur, gi0, jc, 0);
            }
        } else if (grp == 2) {
            if (t >= 1) gemm4<HID, 17>(g_We1i, h0s, gi1, jc, 0);
        } else if (grp == 3) {
            if (t >= 1) gemm4<HID, 15>(g_We1i, h0s, gi1 + GB, jc, 17);
            if (t < TIN) gemm4<NFEAT, 2>(g_We0i, xcur, gi0 + GB, jc, 2);
        } else if (grp == 4) {
            if (t >= 1) gemm4<HID, 16>(g_We1h, h1s, gh1, jc, 0);
        } else {
            if (t >= 1) gemm4<HID, 16>(g_We1h, h1s, gh1 + GB, jc, 16);
        }
        __syncthreads();
        // Phase B: gates l0(t) + gates l1(t-1)
        for (int i = tid; i < 2 * HID * NP; i += NT) {
            if (i < HID * NP) {
                if (t < TIN) gate_dd(h0s, gi0, gh0, b4e0, i);
            } else {
                if (t >= 1) gate_dd(h1s, gi1, gh1, b4e1, i - HID * NP);
            }
        }
        __syncthreads();
    }

    // ====================== decoder (cell1 skewed by 1) =====================
    const float b2 = __ldg(fcb2);

    for (int t = 0; t <= TOUT; t++) {
        // Phase A: balanced gemm segments l0-hh(t) + l1(t-1) (16 units each)
        if (grp == 0) {
            if (t < TOUT) gemm4<HID, 16>(g_Wd0h, h0s, gh0, jc, 0);
        } else if (grp == 1) {
            if (t < TOUT) gemm4<HID, 16>(g_Wd0h, h0s, gh0 + GB, jc, 16);
        } else if (grp == 2) {
            if (t >= 1) gemm4<HID, 16>(g_Wd1i, h0s, gi1, jc, 0);
        } else if (grp == 3) {
            if (t >= 1) gemm4<HID, 16>(g_Wd1i, h0s, gi1 + GB, jc, 16);
        } else if (grp == 4) {
            if (t >= 1) gemm4<HID, 16>(g_Wd1h, h1s, gh1, jc, 0);
        } else {
            if (t >= 1) gemm4<HID, 16>(g_Wd1h, h1s, gh1 + GB, jc, 16);
        }
        __syncthreads();
        // Phase B: gates l1(t-1) -> h1(t-1)
        if (t >= 1)
            for (int i = tid; i < HID * NP; i += NT)
                gate_dd(h1s, gi1, gh1, b4d1, i);
        __syncthreads();
        // Phase C: fc(t-1) (warp p handles pair p) -> pred(t-1), out
        if (t >= 1 && tid < 32 * NP) {
            int p = tid >> 5, l = tid & 31;
            int c0 = 2 * l, c1 = 2 * l + 1;
            const float4* W4 = reinterpret_cast<const float4*>(g_Wfc1);
            ull A0 = 0ull, A1 = 0ull;
#pragma unroll 8
            for (int m = 0; m < 64; m++) {
                float4 w = __ldg(&W4[m * 32 + l]);
                ulonglong2 hm =
                    *reinterpret_cast<const ulonglong2*>(&h1s[p * HID + 2 * m]);
                A0 = ffma2(hm.x, pk2(w.x, w.x), A0);
                A0 = ffma2(hm.y, pk2(w.y, w.y), A0);
                A1 = ffma2(hm.x, pk2(w.z, w.z), A1);
                A1 = ffma2(hm.y, pk2(w.w, w.w), A1);
            }
            float2 v0 = upk(A0), v1 = upk(A1);
            float e0x = fmaxf(v0.x + sfcb1[c0], 0.0f);
            float e0y = fmaxf(v0.y + sfcb1[c0], 0.0f);
            float e1x = fmaxf(v1.x + sfcb1[c1], 0.0f);
            float e1y = fmaxf(v1.y + sfcb1[c1], 0.0f);
            float sx = e0x * sw2[c0] + e1x * sw2[c1];
            float sy = e0y * sw2[c0] + e1y * sw2[c1];
#pragma unroll
            for (int o = 16; o > 0; o >>= 1) {
                sx += __shfl_down_sync(0xffffffffu, sx, o);
                sy += __shfl_down_sync(0xffffffffu, sy, o);
            }
            if (l == 0) {
                float px = fmaxf(sx + b2, 0.0f);
                float py = fmaxf(sy + b2, 0.0f);
                pred2[p] = pk2(px, py);
                int ra = rowbase + 2 * p;
                if (ra < BATCH) out[(size_t)ra * TOUT + (t - 1)] = px;
                if (ra + 1 < BATCH) out[(size_t)(ra + 1) * TOUT + (t - 1)] = py;
            }
        }
        __syncthreads();
        // Phase D: gates l0(t) with pred(t-1) -> h0(t)
        if (t < TOUT)
            for (int i = tid; i < HID * NP; i += NT)
                gate_d0(h0s, gh0, pred2, dw4, b4d0, i);
        __syncthreads();
    }
}

// ---------------------------------------------------------------------------
extern "C" void kernel_launch(void* const* d_in, const int* in_sizes, int n_in,
                              void* d_out, int out_size) {
    (void)in_sizes; (void)n_in; (void)out_size;
    const float* x     = (const float*)d_in[0];
    const float* eWih0 = (const float*)d_in[1];
    const float* eWhh0 = (const float*)d_in[2];
    const float* ebih0 = (const float*)d_in[3];
    const float* ebhh0 = (const float*)d_in[4];
    const float* eWih1 = (const float*)d_in[5];
    const float* eWhh1 = (const float*)d_in[6];
    const float* ebih1 = (const float*)d_in[7];
    const float* ebhh1 = (const float*)d_in[8];
    const float* dWih0 = (const float*)d_in[9];
    const float* dWhh0 = (const float*)d_in[10];
    const float* dbih0 = (const float*)d_in[11];
    const float* dbhh0 = (const float*)d_in[12];
    const float* dWih1 = (const float*)d_in[13];
    const float* dWhh1 = (const float*)d_in[14];
    const float* dbih1 = (const float*)d_in[15];
    const float* dbhh1 = (const float*)d_in[16];
    const float* fcW1  = (const float*)d_in[17];
    const float* fcb1  = (const float*)d_in[18];
    const float* fcW2  = (const float*)d_in[19];
    const float* fcb2  = (const float*)d_in[20];
    float* out = (float*)d_out;

    cudaFuncSetAttribute(gru_main, cudaFuncAttributeMaxDynamicSharedMemorySize,
                         (int)SMEM_BYTES);

    {
        int total = NFEAT * 384 + 6 * HID * 384 + HID * 64;
        int thr = 256;
        tr_all<<<(total + thr - 1) / thr, thr>>>(eWih0, eWhh0, eWih1, eWhh1,
                                                 dWhh0, dWih1, dWhh1, fcW1);
    }

    gru_main<<<NBLK, NT, SMEM_BYTES>>>(x,
                                       ebih0, ebhh0, ebih1, ebhh1,
                                       dWih0,
                                       dbih0, dbhh0, dbih1, dbhh1,
                                       fcb1, fcW2, fcb2,
                                       out);
}

// round 16
// speedup vs baseline: 1.2693x; 1.2693x over previous
#include <cuda_runtime.h>
#include <cstdint>

// ---------------------------------------------------------------------------
// GRUSeq2Seq on GB300 (sm_103a) — round 16
// = Round 14 (best: balanced 5-group C=3 split, layer-skewed 2-phase steps)
//   + n-gate tanh via tanh.approx.f32 (validated: rel_err ~1e-5, 100x margin).
// 147 CTAs x 14 rows. NT=640 = 5 groups x 128 threads, cols jc,+128,+256.
//   grp0: W*0h[0:20)            grp1: W*0h[20:32)+W0i+W*1h[0:4)
//   grp2: W*1i[0:20)            grp3: W*1i[20:32)+W*1h[4:12)
//   grp4: W*1h[12:32)
// Buffers: gi0 x1, gh0 x2, gi1 x2, gh1 x3 partials. fp32 fma.rn.f32x2.
// ---------------------------------------------------------------------------

#define HID   128
#define NFEAT 16
#define TIN   336
#define TOUT  168
#define BATCH 2048
#define NP    7
#define NROW  14
#define NT    640
#define NBLK  147
#define GB    2688        // ull per gate buffer (NP*384)

typedef unsigned long long ull;

__device__ float g_We0i[NFEAT * 384];  // float4 layout [k/4][384][4]
__device__ float g_We0h[HID * 384];
__device__ float g_We1i[HID * 384];
__device__ float g_We1h[HID * 384];
__device__ float g_Wd0h[HID * 384];
__device__ float g_Wd1i[HID * 384];
__device__ float g_Wd1h[HID * 384];
__device__ float g_Wfc1[HID * 64];     // pair layout [k/2][64][2]

__device__ __forceinline__ ull pk2(float lo, float hi) {
    ull r;
    asm("mov.b64 %0, {%1, %2};" : "=l"(r) : "f"(lo), "f"(hi));
    return r;
}
__device__ __forceinline__ float2 upk(ull v) {
    float a, b;
    asm("mov.b64 {%0, %1}, %2;" : "=f"(a), "=f"(b) : "l"(v));
    return make_float2(a, b);
}
__device__ __forceinline__ ull ffma2(ull a, ull b, ull c) {
    ull d;
    asm("fma.rn.f32x2 %0, %1, %2, %3;" : "=l"(d) : "l"(a), "l"(b), "l"(c));
    return d;
}
__device__ __forceinline__ ull add2(ull a, ull b) {
    ull d;
    asm("add.rn.f32x2 %0, %1, %2;" : "=l"(d) : "l"(a), "l"(b));
    return d;
}
// sigmoid via HW tanh: sigma(v) = 0.5*tanh(v/2) + 0.5   (1 MUFU)
__device__ __forceinline__ float sigmf(float v) {
    float t;
    asm("tanh.approx.f32 %0, %1;" : "=f"(t) : "f"(0.5f * v));
    return fmaf(0.5f, t, 0.5f);
}
// n-gate tanh via HW tanh (validated in R15: total rel_err ~1e-5)
__device__ __forceinline__ float tanh_f(float v) {
    float t;
    asm("tanh.approx.f32 %0, %1;" : "=f"(t) : "f"(v));
    return t;
}

// ------------------------- triple-column GEMM segment -----------------------
template <int K, int N4>
__device__ __forceinline__ void gemm3(const float* __restrict__ Wf,
                                      const ull* __restrict__ hs,
                                      ull* __restrict__ dst,
                                      int jc, int k4b) {
    const float4* W4 = reinterpret_cast<const float4*>(Wf);
    ull a0[NP], a1[NP], a2[NP];
#pragma unroll
    for (int p = 0; p < NP; p++) { a0[p] = 0ull; a1[p] = 0ull; a2[p] = 0ull; }
#pragma unroll 4
    for (int i = 0; i < N4; i++) {
        const int k4 = k4b + i;
        const float4* wrow = &W4[k4 * 384 + jc];
        float4 wA = __ldg(wrow);
        float4 wB = __ldg(wrow + 128);
        float4 wC = __ldg(wrow + 256);
        ull wa0 = pk2(wA.x, wA.x), wa1 = pk2(wA.y, wA.y);
        ull wa2 = pk2(wA.z, wA.z), wa3 = pk2(wA.w, wA.w);
        ull wb0 = pk2(wB.x, wB.x), wb1 = pk2(wB.y, wB.y);
        ull wb2 = pk2(wB.z, wB.z), wb3 = pk2(wB.w, wB.w);
        ull wc0 = pk2(wC.x, wC.x), wc1 = pk2(wC.y, wC.y);
        ull wc2 = pk2(wC.z, wC.z), wc3 = pk2(wC.w, wC.w);
#pragma unroll
        for (int p = 0; p < NP; p++) {
            const ull* hp = &hs[p * K + 4 * k4];
            ulonglong2 h01 = *reinterpret_cast<const ulonglong2*>(hp);
            ulonglong2 h23 = *reinterpret_cast<const ulonglong2*>(hp + 2);
            a0[p] = ffma2(h01.x, wa0, a0[p]);
            a1[p] = ffma2(h01.x, wb0, a1[p]);
            a2[p] = ffma2(h01.x, wc0, a2[p]);
            a0[p] = ffma2(h01.y, wa1, a0[p]);
            a1[p] = ffma2(h01.y, wb1, a1[p]);
            a2[p] = ffma2(h01.y, wc1, a2[p]);
            a0[p] = ffma2(h23.x, wa2, a0[p]);
            a1[p] = ffma2(h23.x, wb2, a1[p]);
            a2[p] = ffma2(h23.x, wc2, a2[p]);
            a0[p] = ffma2(h23.y, wa3, a0[p]);
            a1[p] = ffma2(h23.y, wb3, a1[p]);
            a2[p] = ffma2(h23.y, wc3, a2[p]);
        }
    }
#pragma unroll
    for (int p = 0; p < NP; p++) {
        dst[p * 384 + jc]       = a0[p];
        dst[p * 384 + jc + 128] = a1[p];
        dst[p * 384 + jc + 256] = a2[p];
    }
}

// ------------------------- GRU core ----------------------------------------
__device__ __forceinline__ ull gru_core(float2 ir, float2 iz, float2 inn,
                                        float2 hr, float2 hz, float2 hn,
                                        float4 bb, ull hold) {
    float2 h = upk(hold);
    float rx = sigmf(ir.x + hr.x + bb.x);
    float ry = sigmf(ir.y + hr.y + bb.x);
    float zx = sigmf(iz.x + hz.x + bb.y);
    float zy = sigmf(iz.y + hz.y + bb.y);
    float nx = tanh_f(inn.x + bb.z + rx * (hn.x + bb.w));
    float ny = tanh_f(inn.y + bb.z + ry * (hn.y + bb.w));
    return pk2((1.0f - zx) * nx + zx * h.x, (1.0f - zy) * ny + zy * h.y);
}

// gates: gi single, gh dual partials (encoder h0)
__device__ __forceinline__ void gate_12(ull* hs, const ull* gi, const ull* gh,
                                        const float4* b4, int i) {
    int u = i & (HID - 1);
    int p = i >> 7;
    int b0 = p * 384 + u;
    float2 hr = upk(add2(gh[b0], gh[b0 + GB]));
    float2 hz = upk(add2(gh[b0 + HID], gh[b0 + HID + GB]));
    float2 hn = upk(add2(gh[b0 + 2 * HID], gh[b0 + 2 * HID + GB]));
    hs[p * HID + u] = gru_core(upk(gi[b0]), upk(gi[b0 + HID]), upk(gi[b0 + 2 * HID]),
                               hr, hz, hn, b4[u], hs[p * HID + u]);
}

// gates: gi dual, gh triple partials (h1 cells)
__device__ __forceinline__ void gate_23(ull* hs, const ull* gi, const ull* gh,
                                        const float4* b4, int i) {
    int u = i & (HID - 1);
    int p = i >> 7;
    int b0 = p * 384 + u;
    float2 ir  = upk(add2(gi[b0], gi[b0 + GB]));
    float2 iz  = upk(add2(gi[b0 + HID], gi[b0 + HID + GB]));
    float2 inn = upk(add2(gi[b0 + 2 * HID], gi[b0 + 2 * HID + GB]));
    float2 hr  = upk(add2(add2(gh[b0], gh[b0 + GB]), gh[b0 + 2 * GB]));
    float2 hz  = upk(add2(add2(gh[b0 + HID], gh[b0 + HID + GB]),
                          gh[b0 + HID + 2 * GB]));
    float2 hn  = upk(add2(add2(gh[b0 + 2 * HID], gh[b0 + 2 * HID + GB]),
                          gh[b0 + 2 * HID + 2 * GB]));
    hs[p * HID + u] = gru_core(ir, iz, inn, hr, hz, hn, b4[u],
                               hs[p * HID + u]);
}

// decoder cell-0 gates: gh dual partials, gi = pred * dwih0 folded in
__device__ __forceinline__ void gate_d0(ull* hs, const ull* gh,
                                        const ull* pred2, const float4* dw4,
                                        const float4* b4, int i) {
    int u = i & (HID - 1);
    int p = i >> 7;
    int b0 = p * 384 + u;
    float2 pr = upk(pred2[p]);
    float4 w = dw4[u];
    float2 ir = make_float2(pr.x * w.x, pr.y * w.x);
    float2 iz = make_float2(pr.x * w.y, pr.y * w.y);
    float2 inn = make_float2(pr.x * w.z, pr.y * w.z);
    float2 hr = upk(add2(gh[b0], gh[b0 + GB]));
    float2 hz = upk(add2(gh[b0 + HID], gh[b0 + HID + GB]));
    float2 hn = upk(add2(gh[b0 + 2 * HID], gh[b0 + 2 * HID + GB]));
    hs[p * HID + u] = gru_core(ir, iz, inn, hr, hz, hn, b4[u],
                               hs[p * HID + u]);
}

// ------------------------- fused weight transform ---------------------------
__global__ void tr_all(const float* __restrict__ w0, const float* __restrict__ w1,
                       const float* __restrict__ w2, const float* __restrict__ w3,
                       const float* __restrict__ w4, const float* __restrict__ w5,
                       const float* __restrict__ w6, const float* __restrict__ w7) {
    int i = blockIdx.x * blockDim.x + threadIdx.x;
    const int n0 = NFEAT * 384;
    const int nH = HID * 384;
    const int n7 = HID * 64;
    int seg, off;
    if (i < n0) { seg = 0; off = i; }
    else if (i < n0 + 6 * nH) { seg = 1 + (i - n0) / nH; off = (i - n0) % nH; }
    else if (i < n0 + 6 * nH + n7) { seg = 7; off = i - n0 - 6 * nH; }
    else return;

    const float* src = seg == 0 ? w0 : seg == 1 ? w1 : seg == 2 ? w2
                     : seg == 3 ? w3 : seg == 4 ? w4 : seg == 5 ? w5
                     : seg == 6 ? w6 : w7;
    float* dst = seg == 0 ? g_We0i : seg == 1 ? g_We0h : seg == 2 ? g_We1i
               : seg == 3 ? g_We1h : seg == 4 ? g_Wd0h : seg == 5 ? g_Wd1i
               : seg == 6 ? g_Wd1h : g_Wfc1;
    int K = seg == 0 ? NFEAT : HID;
    int J = seg == 7 ? 64 : 384;
    int j = off / K;
    int k = off % K;
    float v = src[off];
    if (seg == 7)
        dst[(k >> 1) * (2 * J) + 2 * j + (k & 1)] = v;
    else
        dst[(k >> 2) * (4 * J) + 4 * j + (k & 3)] = v;
}

// ------------------------- shared memory layout (ull units) -----------------
// h0s 896 | h1s 896 | xs 224 | gi0 GB | gh0 2GB | gi1 2GB | gh1 3GB | pred2 8
// b4 tables 4*128 float4 (1024 ull) | dw4 128 float4 (256) | sfcb1+sw2 (64)
#define SM_ULL (896 + 896 + 224 + 8*GB + 8 + 1024 + 256 + 64)
#define SMEM_BYTES (SM_ULL * 8)   // 198,976 B

__global__ void __launch_bounds__(NT) gru_main(
    const float* __restrict__ x,
    const float* __restrict__ be_ih0, const float* __restrict__ be_hh0,
    const float* __restrict__ be_ih1, const float* __restrict__ be_hh1,
    const float* __restrict__ dwih0,
    const float* __restrict__ bd_ih0, const float* __restrict__ bd_hh0,
    const float* __restrict__ bd_ih1, const float* __restrict__ bd_hh1,
    const float* __restrict__ fcb1, const float* __restrict__ fcw2,
    const float* __restrict__ fcb2,
    float* __restrict__ out) {
    extern __shared__ ull sm[];
    ull* h0s = sm;                 // 896
    ull* h1s = h0s + 896;          // 896
    ull* xs  = h1s + 896;          // 224 (double-buffered 112)
    ull* gi0 = xs + 224;           // GB
    ull* gh0 = gi0 + GB;           // 2GB
    ull* gi1 = gh0 + 2 * GB;       // 2GB
    ull* gh1 = gi1 + 2 * GB;       // 3GB
    ull* pred2 = gh1 + 3 * GB;     // 8
    float4* b4e0 = reinterpret_cast<float4*>(pred2 + 8);   // 128 each
    float4* b4e1 = b4e0 + 128;
    float4* b4d0 = b4e1 + 128;
    float4* b4d1 = b4d0 + 128;
    float4* dw4  = b4d1 + 128;     // 128
    float* sfcb1 = reinterpret_cast<float*>(dw4 + 128);    // 64
    float* sw2   = sfcb1 + 64;

    const int tid = threadIdx.x;
    const int grp = tid >> 7;      // 0..4, warp-uniform
    const int jc  = tid & 127;     // columns jc, jc+128, jc+256
    const int rowbase = blockIdx.x * NROW;

    // ---- init ----
    for (int i = tid; i < 1792; i += NT) h0s[i] = 0ull;
    if (tid < 512) {
        int type = tid >> 7, u = tid & 127;
        const float* bi = type == 0 ? be_ih0 : type == 1 ? be_ih1
                        : type == 2 ? bd_ih0 : bd_ih1;
        const float* bh = type == 0 ? be_hh0 : type == 1 ? be_hh1
                        : type == 2 ? bd_hh0 : bd_hh1;
        float4* dst4 = type == 0 ? b4e0 : type == 1 ? b4e1
                     : type == 2 ? b4d0 : b4d1;
        dst4[u] = make_float4(bi[u] + bh[u], bi[HID + u] + bh[HID + u],
                              bi[2 * HID + u], bh[2 * HID + u]);
    } else if (tid < 640) {
        int u = tid - 512;
        dw4[u] = make_float4(dwih0[u], dwih0[HID + u], dwih0[2 * HID + u], 0.0f);
    }
    if (tid < 64) {
        sfcb1[tid] = fcb1[tid];
        sw2[tid] = fcw2[tid];
    }
    if (tid < 8) pred2[tid] = 0ull;
    for (int i = tid; i < NP * NFEAT; i += NT) {
        int p = i >> 4, c = i & 15;
        int ra = rowbase + 2 * p, rb = ra + 1;
        if (ra > BATCH - 1) ra = BATCH - 1;
        if (rb > BATCH - 1) rb = BATCH - 1;
        xs[p * NFEAT + c] = pk2(x[(size_t)ra * TIN * NFEAT + c],
                                x[(size_t)rb * TIN * NFEAT + c]);
    }
    __syncthreads();

    // ====================== encoder (layer1 skewed by 1) ====================
    for (int t = 0; t <= TIN; t++) {
        // Phase A: stage x(t+1); balanced gemm segments l0(t) + l1(t-1)
        if (t + 1 < TIN) {
            ull* xd = xs + ((t + 1) & 1) * 112;
            for (int i = tid; i < NP * NFEAT; i += NT) {
                int p = i >> 4, c = i & 15;
                int ra = rowbase + 2 * p, rb = ra + 1;
                if (ra > BATCH - 1) ra = BATCH - 1;
                if (rb > BATCH - 1) rb = BATCH - 1;
                xd[p * NFEAT + c] =
                    pk2(x[(size_t)ra * TIN * NFEAT + (size_t)(t + 1) * NFEAT + c],
                        x[(size_t)rb * TIN * NFEAT + (size_t)(t + 1) * NFEAT + c]);
            }
        }
        const ull* xcur = xs + (t & 1) * 112;
        if (grp == 0) {
            if (t < TIN) gemm3<HID, 20>(g_We0h, h0s, gh0, jc, 0);
        } else if (grp == 1) {
            if (t < TIN) {
                gemm3<HID, 12>(g_We0h, h0s, gh0 + GB, jc, 20);
                gemm3<NFEAT, 4>(g_We0i, xcur, gi0, jc, 0);
            }
            if (t >= 1) gemm3<HID, 4>(g_We1h, h1s, gh1, jc, 0);
        } else if (grp == 2) {
            if (t >= 1) gemm3<HID, 20>(g_We1i, h0s, gi1, jc, 0);
        } else if (grp == 3) {
            if (t >= 1) {
                gemm3<HID, 12>(g_We1i, h0s, gi1 + GB, jc, 20);
                gemm3<HID, 8>(g_We1h, h1s, gh1 + GB, jc, 4);
            }
        } else {
            if (t >= 1) gemm3<HID, 20>(g_We1h, h1s, gh1 + 2 * GB, jc, 12);
        }
        __syncthreads();
        // Phase B: gates l0(t) + gates l1(t-1)
        for (int i = tid; i < 2 * HID * NP; i += NT) {
            if (i < HID * NP) {
                if (t < TIN) gate_12(h0s, gi0, gh0, b4e0, i);
            } else {
                if (t >= 1) gate_23(h1s, gi1, gh1, b4e1, i - HID * NP);
            }
        }
        __syncthreads();
    }

    // ====================== decoder (cell1 skewed by 1) =====================
    const float b2 = __ldg(fcb2);

    for (int t = 0; t <= TOUT; t++) {
        // Phase A: balanced gemm segments l0-hh(t) + l1(t-1)
        if (grp == 0) {
            if (t < TOUT) gemm3<HID, 20>(g_Wd0h, h0s, gh0, jc, 0);
        } else if (grp == 1) {
            if (t < TOUT) gemm3<HID, 12>(g_Wd0h, h0s, gh0 + GB, jc, 20);
            if (t >= 1) gemm3<HID, 4>(g_Wd1h, h1s, gh1, jc, 0);
        } else if (grp == 2) {
            if (t >= 1) gemm3<HID, 20>(g_Wd1i, h0s, gi1, jc, 0);
        } else if (grp == 3) {
            if (t >= 1) {
                gemm3<HID, 12>(g_Wd1i, h0s, gi1 + GB, jc, 20);
                gemm3<HID, 8>(g_Wd1h, h1s, gh1 + GB, jc, 4);
            }
        } else {
            if (t >= 1) gemm3<HID, 20>(g_Wd1h, h1s, gh1 + 2 * GB, jc, 12);
        }
        __syncthreads();
        // Phase B: gates l1(t-1) -> h1(t-1)
        if (t >= 1)
            for (int i = tid; i < HID * NP; i += NT)
                gate_23(h1s, gi1, gh1, b4d1, i);
        __syncthreads();
        // Phase C: fc(t-1) (warp p handles pair p) -> pred(t-1), out
        if (t >= 1 && tid < 32 * NP) {
            int p = tid >> 5, l = tid & 31;
            int c0 = 2 * l, c1 = 2 * l + 1;
            const float4* W4 = reinterpret_cast<const float4*>(g_Wfc1);
            ull A0 = 0ull, A1 = 0ull;
#pragma unroll 8
            for (int m = 0; m < 64; m++) {
                float4 w = __ldg(&W4[m * 32 + l]);
                ulonglong2 hm =
                    *reinterpret_cast<const ulonglong2*>(&h1s[p * HID + 2 * m]);
                A0 = ffma2(hm.x, pk2(w.x, w.x), A0);
                A0 = ffma2(hm.y, pk2(w.y, w.y), A0);
                A1 = ffma2(hm.x, pk2(w.z, w.z), A1);
                A1 = ffma2(hm.y, pk2(w.w, w.w), A1);
            }
            float2 v0 = upk(A0), v1 = upk(A1);
            float e0x = fmaxf(v0.x + sfcb1[c0], 0.0f);
            float e0y = fmaxf(v0.y + sfcb1[c0], 0.0f);
            float e1x = fmaxf(v1.x + sfcb1[c1], 0.0f);
            float e1y = fmaxf(v1.y + sfcb1[c1], 0.0f);
            float sx = e0x * sw2[c0] + e1x * sw2[c1];
            float sy = e0y * sw2[c0] + e1y * sw2[c1];
#pragma unroll
            for (int o = 16; o > 0; o >>= 1) {
                sx += __shfl_down_sync(0xffffffffu, sx, o);
                sy += __shfl_down_sync(0xffffffffu, sy, o);
            }
            if (l == 0) {
                float px = fmaxf(sx + b2, 0.0f);
                float py = fmaxf(sy + b2, 0.0f);
                pred2[p] = pk2(px, py);
                int ra = rowbase + 2 * p;
                if (ra < BATCH) out[(size_t)ra * TOUT + (t - 1)] = px;
                if (ra + 1 < BATCH) out[(size_t)(ra + 1) * TOUT + (t - 1)] = py;
            }
        }
        __syncthreads();
        // Phase D: gates l0(t) with pred(t-1) -> h0(t)
        if (t < TOUT)
            for (int i = tid; i < HID * NP; i += NT)
                gate_d0(h0s, gh0, pred2, dw4, b4d0, i);
        __syncthreads();
    }
}

// ---------------------------------------------------------------------------
extern "C" void kernel_launch(void* const* d_in, const int* in_sizes, int n_in,
                              void* d_out, int out_size) {
    (void)in_sizes; (void)n_in; (void)out_size;
    const float* x     = (const float*)d_in[0];
    const float* eWih0 = (const float*)d_in[1];
    const float* eWhh0 = (const float*)d_in[2];
    const float* ebih0 = (const float*)d_in[3];
    const float* ebhh0 = (const float*)d_in[4];
    const float* eWih1 = (const float*)d_in[5];
    const float* eWhh1 = (const float*)d_in[6];
    const float* ebih1 = (const float*)d_in[7];
    const float* ebhh1 = (const float*)d_in[8];
    const float* dWih0 = (const float*)d_in[9];
    const float* dWhh0 = (const float*)d_in[10];
    const float* dbih0 = (const float*)d_in[11];
    const float* dbhh0 = (const float*)d_in[12];
    const float* dWih1 = (const float*)d_in[13];
    const float* dWhh1 = (const float*)d_in[14];
    const float* dbih1 = (const float*)d_in[15];
    const float* dbhh1 = (const float*)d_in[16];
    const float* fcW1  = (const float*)d_in[17];
    const float* fcb1  = (const float*)d_in[18];
    const float* fcW2  = (const float*)d_in[19];
    const float* fcb2  = (const float*)d_in[20];
    float* out = (float*)d_out;

    cudaFuncSetAttribute(gru_main, cudaFuncAttributeMaxDynamicSharedMemorySize,
                         (int)SMEM_BYTES);

    {
        int total = NFEAT * 384 + 6 * HID * 384 + HID * 64;
        int thr = 256;
        tr_all<<<(total + thr - 1) / thr, thr>>>(eWih0, eWhh0, eWih1, eWhh1,
                                                 dWhh0, dWih1, dWhh1, fcW1);
    }

    gru_main<<<NBLK, NT, SMEM_BYTES>>>(x,
                                       ebih0, ebhh0, ebih1, ebhh1,
                                       dWih0,
                                       dbih0, dbhh0, dbih1, dbhh1,
                                       fcb1, fcW2, fcb2,
                                       out);
}